// round 2
// baseline (speedup 1.0000x reference)
#include <cuda_runtime.h>
#include <cstdint>

// Shapes (fixed by the problem)
#define B 8
#define N 256
#define IN 64
#define F 64          // H*D
#define H 8
#define D 8
#define RPC 4         // rows (i values) per CTA in the attention kernel

#define L2E 1.4426950408889634f

// Scratch (allocation-free rule: __device__ globals)
__device__ float g_Q[B * N * F];
__device__ float g_K[B * N * F];   // pre-scaled by D^-0.5
__device__ float g_V[B * N * F];

// ---------------------------------------------------------------------------
// Kernel A: Q/K/V projections.  grid = B*N/4 blocks, 256 threads (4 rows x 64 f)
// ---------------------------------------------------------------------------
__global__ void __launch_bounds__(256) qkv_kernel(
    const float* __restrict__ h,
    const float* __restrict__ Wq,
    const float* __restrict__ Wk,
    const float* __restrict__ Wv)
{
    __shared__ float hs[4][IN];
    int r   = threadIdx.x >> 6;    // 0..3
    int f   = threadIdx.x & 63;    // 0..63
    int row = blockIdx.x * 4 + r;  // global b*N+i row, 0..2047

    hs[r][f] = h[row * IN + f];
    __syncthreads();

    float aq = 0.f, ak = 0.f, av = 0.f;
#pragma unroll
    for (int k = 0; k < IN; k++) {
        float hv = hs[r][k];
        aq = fmaf(hv, Wq[k * F + f], aq);
        ak = fmaf(hv, Wk[k * F + f], ak);
        av = fmaf(hv, Wv[k * F + f], av);
    }
    g_Q[row * F + f] = aq;
    g_K[row * F + f] = ak * 0.35355339059327373f;  // D^-0.5, D=8
    g_V[row * F + f] = av;
}

// ---------------------------------------------------------------------------
// Kernel B: fused qk + softmax(streaming, fixed-shift) + weighted sum.
// grid = B * (N/RPC) = 512 blocks, 128 threads (warp per row, lane owns 2 f's)
// ---------------------------------------------------------------------------
__global__ void __launch_bounds__(128) attn_kernel(
    const float* __restrict__ e_att,
    const float* __restrict__ e_value,
    const uint32_t* __restrict__ attn_mask,   // 4-byte elems; true <=> nonzero bits
    float* __restrict__ out)
{
    __shared__ float qk_s[RPC][N][H];   // 32 KB; holds qk*log2e - M2 after transform
    __shared__ float q_s[RPC][F];       // 1 KB
    __shared__ float msk_s[RPC][N];     // 4 KB (0.0/1.0)

    const int blk  = blockIdx.x;
    const int b    = blk >> 6;          // 64 blocks per batch (N/RPC = 64)
    const int i0   = (blk & 63) * RPC;
    const int tid  = threadIdx.x;
    const int wid  = tid >> 5;
    const int lane = tid & 31;

    // ---- load Q rows + mask into smem ----
    for (int t = tid; t < RPC * F; t += 128) {
        int r = t >> 6, f = t & 63;
        q_s[r][f] = g_Q[(b * N + i0 + r) * F + f];
    }
    for (int t = tid; t < RPC * N; t += 128) {
        int r = t >> 8, j = t & 255;
        // works for int32 (1/0) and float32 (1.0f/0.0f) encodings alike
        msk_s[r][j] = (attn_mask[(b * N + i0 + r) * N + j] != 0u) ? 1.0f : 0.0f;
    }
    __syncthreads();

    // ---- phase 1: qk[r][j][h] = dot8(Q[r,h,:], K[b,j,h,:]) ----
    {
        const int h  = lane >> 2;       // 0..7
        const int jm = lane & 3;        // 0..3
        float qreg[RPC][8];
#pragma unroll
        for (int r = 0; r < RPC; r++)
#pragma unroll
            for (int d = 0; d < 8; d++)
                qreg[r][d] = q_s[r][h * 8 + d];

        const float4* Kb = (const float4*)(g_K + b * N * F);
        for (int jg = wid * 16; jg < wid * 16 + 16; jg++) {
            int j = jm + 4 * jg;
            float4 k0 = Kb[j * 16 + h * 2];
            float4 k1 = Kb[j * 16 + h * 2 + 1];
#pragma unroll
            for (int r = 0; r < RPC; r++) {
                float s = qreg[r][0] * k0.x;
                s = fmaf(qreg[r][1], k0.y, s);
                s = fmaf(qreg[r][2], k0.z, s);
                s = fmaf(qreg[r][3], k0.w, s);
                s = fmaf(qreg[r][4], k1.x, s);
                s = fmaf(qreg[r][5], k1.y, s);
                s = fmaf(qreg[r][6], k1.z, s);
                s = fmaf(qreg[r][7], k1.w, s);
                qk_s[r][j][h] = s;
            }
        }
    }
    __syncthreads();

    // ---- phase 2: per-row shift M = rowmax(qk)+10; transform qk' = qk*L2E - M*L2E ----
    {
        const int r = wid;  // warp handles its own row
        float* qf = &qk_s[r][0][0];
        float mx = -1e30f;
        for (int t = lane; t < N * H; t += 32) mx = fmaxf(mx, qf[t]);
#pragma unroll
        for (int o = 16; o; o >>= 1) mx = fmaxf(mx, __shfl_xor_sync(0xffffffffu, mx, o));
        float M2 = (mx + 10.0f) * L2E;
        for (int t = lane; t < N * H; t += 32)
            qf[t] = fmaf(qf[t], L2E, -M2);
    }
    __syncthreads();

    // ---- phase 3: streaming softmax + weighted accumulation ----
    const int r = wid;
    const int i = i0 + r;
    const int h = lane >> 2;

    const float2* ea = (const float2*)(e_att   + (size_t)(b * N + i) * N * F) + lane;
    const float2* ev = (const float2*)(e_value + (size_t)(b * N + i) * N * F) + lane;
    const float2* Vb = (const float2*)(g_V + b * N * F) + lane;

    float l0 = 0.f, l1 = 0.f, a0 = 0.f, a1 = 0.f;

#pragma unroll 4
    for (int j = 0; j < N; j++) {
        float2 eav = ea[j * 32];
        float2 evv = ev[j * 32];
        float2 vv  = Vb[j * 32];
        float  qk  = qk_s[r][j][h];     // already qk*L2E - M2
        float  mf  = msk_s[r][j];

        float p0 = exp2f(fmaf(eav.x, L2E, qk)) * mf;
        float p1 = exp2f(fmaf(eav.y, L2E, qk)) * mf;
        l0 += p0;
        l1 += p1;
        a0 = fmaf(p0, vv.x + evv.x, a0);
        a1 = fmaf(p1, vv.y + evv.y, a1);
    }

    float2 o;
    o.x = (l0 > 0.f) ? a0 / l0 : 0.f;
    o.y = (l1 > 0.f) ? a1 / l1 : 0.f;
    ((float2*)(out + (size_t)(b * N + i) * F))[lane] = o;
}

// ---------------------------------------------------------------------------
extern "C" void kernel_launch(void* const* d_in, const int* in_sizes, int n_in,
                              void* d_out, int out_size)
{
    const float*    h       = (const float*)d_in[0];
    const float*    e_att   = (const float*)d_in[1];
    const float*    e_value = (const float*)d_in[2];
    const uint32_t* mask    = (const uint32_t*)d_in[3];
    const float*    Wq      = (const float*)d_in[4];
    const float*    Wk      = (const float*)d_in[5];
    const float*    Wv      = (const float*)d_in[6];
    float*          out     = (float*)d_out;

    qkv_kernel<<<(B * N) / 4, 256>>>(h, Wq, Wk, Wv);
    attn_kernel<<<B * (N / RPC), 128>>>(e_att, e_value, mask, out);
}